// round 15
// baseline (speedup 1.0000x reference)
#include <cuda_runtime.h>
#include <cuda_bf16.h>
#include <math.h>

#define BB   128
#define TT   256
#define HH   1024
#define KG   256
#define NBLK 128
#define NJ   8
#define NTH  512

typedef unsigned long long u64;
typedef unsigned int u32;

/* Scratch (static device globals; no runtime allocation). */
__device__ float4 g_pre0[(size_t)TT * KG * BB];   /* [t][j4][b] fp32 */
__device__ uint4  g_xfrag[2][(size_t)TT * 16384]; /* [hi/lo][t][mt*64+kt][lane] A-frags of x */
__device__ uint2  g_wfrag[2][64 * 128 * 32];      /* [hi/lo][(kt*128+jt)*32+lane] B-frags of Wi0 */
__device__ uint4  g_A0[2][2][16384];              /* [parity][hi/lo] layer-0 h */
__device__ uint4  g_A1[2][2][16384];              /* [parity][hi/lo] layer-1 h */
__device__ u32    g_flags[NBLK * 64];

/* ---------------- helpers ---------------- */
__device__ __forceinline__ uint4 ldcg4(const uint4* p) {
    uint4 v;
    asm("ld.global.cg.v4.u32 {%0,%1,%2,%3}, [%4];"
        : "=r"(v.x), "=r"(v.y), "=r"(v.z), "=r"(v.w) : "l"(p));
    return v;
}
__device__ __forceinline__ uint2 ldcg2u(const uint2* p) {
    uint2 v;
    asm("ld.global.cg.v2.u32 {%0,%1}, [%2];" : "=r"(v.x), "=r"(v.y) : "l"(p));
    return v;
}
__device__ __forceinline__ void mma16816(float* d, uint4 a, uint2 b) {
    asm("mma.sync.aligned.m16n8k16.row.col.f32.bf16.bf16.f32 "
        "{%0,%1,%2,%3}, {%4,%5,%6,%7}, {%8,%9}, {%0,%1,%2,%3};"
        : "+f"(d[0]), "+f"(d[1]), "+f"(d[2]), "+f"(d[3])
        : "r"(a.x), "r"(a.y), "r"(a.z), "r"(a.w), "r"(b.x), "r"(b.y));
}
__device__ __forceinline__ u32 bfpack(float x, float y) {
    unsigned short lx = __bfloat16_as_ushort(__float2bfloat16(x));
    unsigned short ly = __bfloat16_as_ushort(__float2bfloat16(y));
    return (u32)lx | ((u32)ly << 16);
}
__device__ __forceinline__ float bfr(float x) { return __bfloat162float(__float2bfloat16(x)); }
__device__ __forceinline__ float bflo(u32 v) { return __bfloat162float(__ushort_as_bfloat16((unsigned short)(v & 0xffff))); }
__device__ __forceinline__ float bfhi(u32 v) { return __bfloat162float(__ushort_as_bfloat16((unsigned short)(v >> 16))); }

/* ------------------------------------------------------------------ */
/* Kernel 0: x -> split-bf16 A-fragment planes. grid (256 t, 8 mt).    */
/* ------------------------------------------------------------------ */
__global__ __launch_bounds__(256) void x_convert(const float* __restrict__ x)
{
    if (blockIdx.x == 0 && blockIdx.y == 0 && threadIdx.x < NBLK)
        g_flags[threadIdx.x * 64] = 0u;

    const int t    = blockIdx.x;
    const int mt   = blockIdx.y;
    const int th   = threadIdx.x;
    const int w    = th >> 5;
    const int lane = th & 31;

    const int r  = mt * 16 + (lane >> 2);
    const float* b0 = x + ((size_t)r * TT + t) * HH;
    const float* b1 = x + ((size_t)(r + 8) * TT + t) * HH;

    for (int kt = w; kt < 64; kt += 8) {
        int k0 = kt * 16 + (lane & 3) * 2;
        float2 v00 = *(const float2*)(b0 + k0);
        float2 v10 = *(const float2*)(b1 + k0);
        float2 v01 = *(const float2*)(b0 + k0 + 8);
        float2 v11 = *(const float2*)(b1 + k0 + 8);
        uint4 hi, lo;
        hi.x = bfpack(v00.x, v00.y);
        hi.y = bfpack(v10.x, v10.y);
        hi.z = bfpack(v01.x, v01.y);
        hi.w = bfpack(v11.x, v11.y);
        lo.x = bfpack(v00.x - bfr(v00.x), v00.y - bfr(v00.y));
        lo.y = bfpack(v10.x - bfr(v10.x), v10.y - bfr(v10.y));
        lo.z = bfpack(v01.x - bfr(v01.x), v01.y - bfr(v01.y));
        lo.w = bfpack(v11.x - bfr(v11.x), v11.y - bfr(v11.y));
        size_t fo = (size_t)t * 16384 + (mt * 64 + kt) * 32 + lane;
        g_xfrag[0][fo] = hi;
        g_xfrag[1][fo] = lo;
    }
}

/* ------------------------------------------------------------------ */
/* Kernel 0b: Wi0 -> split-bf16 B-fragment planes. grid 64 (kt).       */
/* ------------------------------------------------------------------ */
__global__ __launch_bounds__(256) void w_convert(const float* __restrict__ Wi)
{
    const int kt = blockIdx.x;
    for (int idx = threadIdx.x; idx < 128 * 32; idx += 256) {
        int jt = idx >> 5, l = idx & 31;
        int n  = jt * 8 + (l >> 2);
        int k0 = kt * 16 + (l & 3) * 2;
        float w00 = Wi[(size_t)k0 * HH + n];
        float w01 = Wi[(size_t)(k0 + 1) * HH + n];
        float w10 = Wi[(size_t)(k0 + 8) * HH + n];
        float w11 = Wi[(size_t)(k0 + 9) * HH + n];
        uint2 hi, lo;
        hi.x = bfpack(w00, w01);
        hi.y = bfpack(w10, w11);
        lo.x = bfpack(w00 - bfr(w00), w01 - bfr(w01));
        lo.y = bfpack(w10 - bfr(w10), w11 - bfr(w11));
        size_t fo = ((size_t)kt * 128 + jt) * 32 + l;
        g_wfrag[0][fo] = hi;
        g_wfrag[1][fo] = lo;
    }
}

/* ------------------------------------------------------------------ */
/* Kernel 1: pre0 = x @ Wi0 + bi0 on tensor cores (unchanged R13).     */
/* ------------------------------------------------------------------ */
__global__ __launch_bounds__(NTH) void pre_mma(const float* __restrict__ bi)
{
    const int jb   = blockIdx.x;
    const int t    = blockIdx.y;
    const int wid  = threadIdx.x >> 5;
    const int lane = threadIdx.x & 31;
    const int mt   = wid & 7;
    const int nh   = wid >> 3;
    const int jt0  = jb * 8 + nh * 4;

    const uint4* pXh = g_xfrag[0] + (size_t)t * 16384 + (size_t)(mt * 64) * 32 + lane;
    const uint4* pXl = g_xfrag[1] + (size_t)t * 16384 + (size_t)(mt * 64) * 32 + lane;
    const uint2* pWh = g_wfrag[0] + (size_t)jt0 * 32 + lane;
    const uint2* pWl = g_wfrag[1] + (size_t)jt0 * 32 + lane;

    float acc[4][4];
#pragma unroll
    for (int nt = 0; nt < 4; ++nt)
#pragma unroll
        for (int r = 0; r < 4; ++r) acc[nt][r] = 0.0f;

    uint4 Xh0, Xl0, Xh1, Xl1;
    uint2 Wh0[4], Wl0[4], Wh1[4], Wl1[4];

    Xh0 = ldcg4(pXh); Xl0 = ldcg4(pXl);
#pragma unroll
    for (int nt = 0; nt < 4; ++nt) {
        Wh0[nt] = ldcg2u(pWh + nt * 32);
        Wl0[nt] = ldcg2u(pWl + nt * 32);
    }

#pragma unroll 1
    for (int kt = 0; kt < 64; kt += 2) {
        if (kt + 1 < 64) {
            Xh1 = ldcg4(pXh + (kt + 1) * 32);
            Xl1 = ldcg4(pXl + (kt + 1) * 32);
#pragma unroll
            for (int nt = 0; nt < 4; ++nt) {
                Wh1[nt] = ldcg2u(pWh + ((kt + 1) * 128 + nt) * 32);
                Wl1[nt] = ldcg2u(pWl + ((kt + 1) * 128 + nt) * 32);
            }
        }
#pragma unroll
        for (int nt = 0; nt < 4; ++nt) {
            mma16816(acc[nt], Xh0, Wh0[nt]);
            mma16816(acc[nt], Xh0, Wl0[nt]);
            mma16816(acc[nt], Xl0, Wh0[nt]);
        }
        if (kt + 2 < 64) {
            Xh0 = ldcg4(pXh + (kt + 2) * 32);
            Xl0 = ldcg4(pXl + (kt + 2) * 32);
#pragma unroll
            for (int nt = 0; nt < 4; ++nt) {
                Wh0[nt] = ldcg2u(pWh + ((kt + 2) * 128 + nt) * 32);
                Wl0[nt] = ldcg2u(pWl + ((kt + 2) * 128 + nt) * 32);
            }
        }
#pragma unroll
        for (int nt = 0; nt < 4; ++nt) {
            mma16816(acc[nt], Xh1, Wh1[nt]);
            mma16816(acc[nt], Xh1, Wl1[nt]);
            mma16816(acc[nt], Xl1, Wh1[nt]);
        }
    }

    const int r = mt * 16 + (lane >> 2);
    float* preF = (float*)g_pre0;
#pragma unroll
    for (int nt = 0; nt < 4; ++nt) {
        int col = (jt0 + nt) * 8 + (lane & 3) * 2;
        float b0v = __ldg(&bi[col]);
        float b1v = __ldg(&bi[col + 1]);
        int jg4 = col >> 2, cl = col & 3;
        size_t base = ((size_t)t * KG + jg4) * BB;
        float2 v0 = make_float2(acc[nt][0] + b0v, acc[nt][1] + b1v);
        float2 v1 = make_float2(acc[nt][2] + b0v, acc[nt][3] + b1v);
        *(float2*)(preF + (base + r) * 4 + cl)     = v0;
        *(float2*)(preF + (base + r + 8) * 4 + cl) = v1;
    }
}

/* ---------------- distributed grid barrier ---------------- */
__device__ __forceinline__ void grid_arrive(int cta, int th, u32 ph)
{
    __syncthreads();
    if (th == 0) {
        asm volatile("st.release.gpu.global.u32 [%0], %1;"
                     :: "l"(&g_flags[cta * 64]), "r"(ph) : "memory");
    }
}
__device__ __forceinline__ void grid_wait(int th, u32 ph)
{
    if (th < NBLK) {
        u32 v;
        do {
            asm volatile("ld.acquire.gpu.global.u32 %0, [%1];"
                         : "=r"(v) : "l"(&g_flags[th * 64]) : "memory");
        } while (v < ph);
    }
    __syncthreads();
}

/* Load A frags (4 planes) for m-tile MT at k-tile KT into stage R. */
#define LOADMT(R, MT, KT)                                                    \
    {                                                                        \
        int fo_ = ((MT) * 64 + (KT)) * 32 + lane;                            \
        R##h0 = ldcg4(pA0h + fo_);  R##l0 = ldcg4(pA0l + fo_);               \
        R##h1 = ldcg4(pA1h + fo_);  R##l1 = ldcg4(pA1l + fo_);               \
    }

/* Load shared weight frags for k-tile KT (reused by both m-tiles). */
#define LDW(KT)                                                              \
    {                                                                        \
        int kt_ = (KT);                                                      \
        w0h = sB2[0 * 2048 + kt_ * 32 + lane];                               \
        w0l = sB2[1 * 2048 + kt_ * 32 + lane];                               \
        w1h = sB2[2 * 2048 + kt_ * 32 + lane];                               \
        w1l = sB2[3 * 2048 + kt_ * 32 + lane];                               \
        w2h = sB2[4 * 2048 + kt_ * 32 + lane];                               \
        w2l = sB2[5 * 2048 + kt_ * 32 + lane];                               \
    }

/* 9 MMAs for one m-tile using the shared weight frags. */
#define COMPM(R, Q1, Q1X, Q0)                                                \
    mma16816(Q1,  R##h0, w0h);                                               \
    mma16816(Q1X, R##h0, w0l);                                               \
    mma16816(Q1X, R##l0, w0h);                                               \
    mma16816(Q1,  R##h1, w1h);                                               \
    mma16816(Q1X, R##h1, w1l);                                               \
    mma16816(Q1X, R##l1, w1h);                                               \
    mma16816(Q0,  R##h0, w2h);                                               \
    mma16816(Q0,  R##h0, w2l);                                               \
    mma16816(Q0,  R##l0, w2h);

/* ------------------------------------------------------------------ */
/* Kernel 2: persistent RNN on tensor cores, mt-paired warps.          */
/* 16 warps = 4 mt-pairs x 4 K-quarters; weight LDS halved.            */
/* ------------------------------------------------------------------ */
__global__ __launch_bounds__(NTH, 1) void rnn_persist(const float* __restrict__ h0,
                                                      const float* __restrict__ Wi,
                                                      const float* __restrict__ bi,
                                                      const float* __restrict__ Wh,
                                                      const float* __restrict__ bh,
                                                      float* __restrict__ out)
{
    extern __shared__ u32 smemU[];
    u32*   sBu = smemU;                       /* 24576 u32 = 96KB weight frags */
    const uint2* sB2 = (const uint2*)smemU;
    float* sr  = (float*)(smemU + 24576);     /* acc1 partials: [4kh][8col][130] */
    float* sr0 = sr + 4160;                   /* acc0 partials */

    const int cta  = blockIdx.x;
    const int th   = threadIdx.x;
    const int wid  = th >> 5;
    const int lane = th & 31;
    const int mtp  = wid & 3;          /* m-tile pair 0..3 */
    const int kh   = wid >> 2;         /* K quarter 0..3 */
    const int mt0g = mtp * 2;
    const int mt1g = mtp * 2 + 1;
    const int j0   = cta * NJ;

    const int frow = th >> 2;
    const int c0   = (th & 3) * 2;
    const int fjg4 = (j0 + c0) >> 2;
    const int fcl  = c0 & 3;
    const int colg = j0 + c0;
    const int wmt  = frow >> 4, wq = frow & 7, wrsel = (frow >> 3) & 1;
    const int wkt  = colg >> 4, wkb = (colg & 7) >> 1, wkhigh = (colg >> 3) & 1;
    const int wadd = (((wmt * 64 + wkt) * 32) + wq * 4 + wkb) * 4 + wrsel + 2 * wkhigh;

    const float* Wi1g = Wi + (size_t)HH * HH;
    const float* Wh1g = Wh + (size_t)HH * HH;

    /* one-time: pack weights into bf16 hi/lo MMA fragments (R11 layout). */
    for (int idx = th; idx < 24576; idx += NTH) {
        int ms = idx >> 12;
        int m  = ms >> 1, s = ms & 1;
        int rem = idx & 4095;
        int kt = rem >> 6, lr = rem & 63;
        int l  = lr >> 1, r = lr & 1;
        int n  = l >> 2;
        int k0 = kt * 16 + (l & 3) * 2 + r * 8;
        const float* M = (m == 0) ? Wi1g : (m == 1) ? Wh1g : Wh;
        float w0 = M[(size_t)k0 * HH + j0 + n];
        float w1 = M[(size_t)(k0 + 1) * HH + j0 + n];
        if (s == 1) { w0 = w0 - bfr(w0); w1 = w1 - bfr(w1); }
        sBu[idx] = bfpack(w0, w1);
    }

    const float bs1_0 = __ldg(&bi[HH + colg])     + __ldg(&bh[HH + colg]);
    const float bs1_1 = __ldg(&bi[HH + colg + 1]) + __ldg(&bh[HH + colg + 1]);
    const float b0r_0 = __ldg(&bh[colg]);
    const float b0r_1 = __ldg(&bh[colg + 1]);

    /* h1 init -> A1 planes parity 1. */
    {
        float y0 = h0[HH + colg], y1 = h0[HH + colg + 1];
        ((u32*)g_A1[1][0])[wadd] = bfpack(y0, y1);
        ((u32*)g_A1[1][1])[wadd] = bfpack(y0 - bfr(y0), y1 - bfr(y1));
    }
    __syncthreads();

    /* hn0[0] init: dot0[col] = h0_l0 @ Wh0 via split-bf16 frags. */
    {
        int icol = th >> 6, ipart = th & 63;
        float dot = 0.0f;
        for (int e = 0; e < 16; ++e) {
            int k = ipart * 16 + e;
            int l = icol * 4 + ((k & 7) >> 1);
            int r = (k >> 3) & 1;
            u32 vh = sBu[4 * 4096 + ipart * 64 + l * 2 + r];
            u32 vl = sBu[5 * 4096 + ipart * 64 + l * 2 + r];
            float w = ((k & 1) ? bfhi(vh) : bflo(vh)) + ((k & 1) ? bfhi(vl) : bflo(vl));
            dot = fmaf(w, h0[k], dot);
        }
        sr[icol * 64 + ipart] = dot;
    }
    __syncthreads();
    {
        float dv0 = 0.0f, dv1 = 0.0f;
#pragma unroll 8
        for (int p = 0; p < 64; ++p) {
            dv0 += sr[c0 * 64 + p];
            dv1 += sr[(c0 + 1) * 64 + p];
        }
        const float* preF = (const float*)g_pre0;
        float p0v = preF[((size_t)fjg4 * BB + frow) * 4 + fcl];
        float p1v = preF[((size_t)fjg4 * BB + frow) * 4 + fcl + 1];
        float y0 = tanhf(p0v + dv0 + b0r_0);
        float y1 = tanhf(p1v + dv1 + b0r_1);
        ((u32*)g_A0[0][0])[wadd] = bfpack(y0, y1);
        ((u32*)g_A0[0][1])[wadd] = bfpack(y0 - bfr(y0), y1 - bfr(y1));
    }

    u32 ph = 1;
    grid_arrive(cta, th, ph);
    grid_wait(th, ph);
    ++ph;

    const int rrow0 = mt0g * 16 + (lane >> 2);
    const int rrow1 = mt1g * 16 + (lane >> 2);
    const int ccol  = (lane & 3) * 2;

    for (int t = 0; t < TT; ++t) {
        const uint4* pA0h = g_A0[t & 1][0];
        const uint4* pA0l = g_A0[t & 1][1];
        const uint4* pA1h = g_A1[(t + 1) & 1][0];
        const uint4* pA1l = g_A1[(t + 1) & 1][1];

        float2 pn = make_float2(0.0f, 0.0f);
        if (t < TT - 1) {
            const float* pp = (const float*)g_pre0 +
                ((size_t)((size_t)(t + 1) * KG + fjg4) * BB + frow) * 4 + fcl;
            asm("ld.global.cg.v2.f32 {%0,%1}, [%2];" : "=f"(pn.x), "=f"(pn.y) : "l"(pp));
        }

        float q1a[4]  = {0, 0, 0, 0}, q1xa[4] = {0, 0, 0, 0}, q0a[4] = {0, 0, 0, 0};
        float q1b[4]  = {0, 0, 0, 0}, q1xb[4] = {0, 0, 0, 0}, q0b[4] = {0, 0, 0, 0};

        {
            const int ktb = kh * 16;
            uint2 w0h, w0l, w1h, w1l, w2h, w2l;
            uint4 Ch0, Cl0, Ch1, Cl1;        /* stage C: mt0 */
            uint4 Dh0, Dl0, Dh1, Dl1;        /* stage D: mt1 */
            uint4 Eh0, El0, Eh1, El1;        /* stage E: mt0 next */
            uint4 Fh0, Fl0, Fh1, Fl1;        /* stage F: mt1 next */
            LOADMT(C, mt0g, ktb);
            LOADMT(D, mt1g, ktb);
#pragma unroll 1
            for (int kt = 0; kt < 16; kt += 2) {
                LDW(ktb + kt);
                LOADMT(E, mt0g, ktb + kt + 1);
                COMPM(C, q1a, q1xa, q0a);
                LOADMT(F, mt1g, ktb + kt + 1);
                COMPM(D, q1b, q1xb, q0b);
                LDW(ktb + kt + 1);
                if (kt + 2 < 16) { LOADMT(C, mt0g, ktb + kt + 2); }
                COMPM(E, q1a, q1xa, q0a);
                if (kt + 2 < 16) { LOADMT(D, mt1g, ktb + kt + 2); }
                COMPM(F, q1b, q1xb, q0b);
            }
        }

        /* write partials: [kh][col][row(130)] for acc1 and acc0. */
        {
            int b = (kh * 8 + ccol) * 130;
            sr [b + rrow0]           = q1a[0] + q1xa[0];
            sr [b + 130 + rrow0]     = q1a[1] + q1xa[1];
            sr [b + rrow0 + 8]       = q1a[2] + q1xa[2];
            sr [b + 130 + rrow0 + 8] = q1a[3] + q1xa[3];
            sr [b + rrow1]           = q1b[0] + q1xb[0];
            sr [b + 130 + rrow1]     = q1b[1] + q1xb[1];
            sr [b + rrow1 + 8]       = q1b[2] + q1xb[2];
            sr [b + 130 + rrow1 + 8] = q1b[3] + q1xb[3];
            sr0[b + rrow0]           = q0a[0];
            sr0[b + 130 + rrow0]     = q0a[1];
            sr0[b + rrow0 + 8]       = q0a[2];
            sr0[b + 130 + rrow0 + 8] = q0a[3];
            sr0[b + rrow1]           = q0b[0];
            sr0[b + 130 + rrow1]     = q0b[1];
            sr0[b + rrow1 + 8]       = q0b[2];
            sr0[b + 130 + rrow1 + 8] = q0b[3];
        }
        __syncthreads();

        /* final pass: (frow, c0..c0+1), 4-way kh reduction. */
        {
            float s1_0 = 0.0f, s1_1 = 0.0f;
#pragma unroll
            for (int k2 = 0; k2 < 4; ++k2) {
                s1_0 += sr[(k2 * 8 + c0) * 130 + frow];
                s1_1 += sr[(k2 * 8 + c0 + 1) * 130 + frow];
            }
            float y0 = tanhf(s1_0 + bs1_0);
            float y1 = tanhf(s1_1 + bs1_1);

            ((u32*)g_A1[t & 1][0])[wadd] = bfpack(y0, y1);
            ((u32*)g_A1[t & 1][1])[wadd] = bfpack(y0 - bfr(y0), y1 - bfr(y1));

            if (t < TT - 1) {
                float s0_0 = 0.0f, s0_1 = 0.0f;
#pragma unroll
                for (int k2 = 0; k2 < 4; ++k2) {
                    s0_0 += sr0[(k2 * 8 + c0) * 130 + frow];
                    s0_1 += sr0[(k2 * 8 + c0 + 1) * 130 + frow];
                }
                float z0 = tanhf(s0_0 + pn.x + b0r_0);
                float z1 = tanhf(s0_1 + pn.y + b0r_1);
                ((u32*)g_A0[(t + 1) & 1][0])[wadd] = bfpack(z0, z1);
                ((u32*)g_A0[(t + 1) & 1][1])[wadd] = bfpack(z0 - bfr(z0), z1 - bfr(z1));

                grid_arrive(cta, th, ph);
                out[((size_t)frow * TT + t) * HH + colg]     = y0;
                out[((size_t)frow * TT + t) * HH + colg + 1] = y1;
                grid_wait(th, ph);
                ++ph;
            } else {
                out[((size_t)frow * TT + t) * HH + colg]     = y0;
                out[((size_t)frow * TT + t) * HH + colg + 1] = y1;
                float* hn = out + (size_t)BB * TT * HH;
                hn[(size_t)(frow * 2 + 1) * HH + colg]     = y0;
                hn[(size_t)(frow * 2 + 1) * HH + colg + 1] = y1;
                u32 vh = ((const u32*)g_A0[t & 1][0])[wadd];
                u32 vl = ((const u32*)g_A0[t & 1][1])[wadd];
                hn[(size_t)(frow * 2) * HH + colg]     = bflo(vh) + bflo(vl);
                hn[(size_t)(frow * 2) * HH + colg + 1] = bfhi(vh) + bfhi(vl);
            }
        }
    }
}

/* ------------------------------------------------------------------ */
extern "C" void kernel_launch(void* const* d_in, const int* in_sizes, int n_in,
                              void* d_out, int out_size)
{
    const float* x  = (const float*)d_in[0];
    const float* h0 = (const float*)d_in[1];
    const float* Wi = (const float*)d_in[2];
    const float* bi = (const float*)d_in[3];
    const float* Wh = (const float*)d_in[4];
    const float* bh = (const float*)d_in[5];
    float* out = (float*)d_out;

    x_convert<<<dim3(256, 8), 256>>>(x);
    w_convert<<<64, 256>>>(Wi);
    pre_mma<<<dim3(16, 256), NTH>>>(bi);

    size_t smem = 24576 * sizeof(u32) + (2 * 4160 + 64) * sizeof(float);   /* ~129 KB */
    cudaFuncSetAttribute(rnn_persist, cudaFuncAttributeMaxDynamicSharedMemorySize, (int)smem);
    rnn_persist<<<NBLK, NTH, smem>>>(h0, Wi, bi, Wh, bh, out);
}